// round 7
// baseline (speedup 1.0000x reference)
#include <cuda_runtime.h>
#include <cuda_bf16.h>
#include <cstdint>

// ---- problem constants ----
#define B_    8
#define N1_   8192
#define N2_   2048
#define C1_   128
#define C2_   256
#define O1_   256
#define O2_   256

// ---- device scratch ----
__device__ __align__(16) __nv_bfloat16 g_W1a_hi[O1_ * C2_], g_W1a_lo[O1_ * C2_];
__device__ __align__(16) __nv_bfloat16 g_W1b_hi[O1_ * C1_], g_W1b_lo[O1_ * C1_];
__device__ __align__(16) __nv_bfloat16 g_W2_hi [O2_ * O1_], g_W2_lo [O2_ * O1_];
__device__ float g_b1eff[O1_], g_b2eff[O2_];
__device__ __align__(16) __nv_bfloat16 g_f1T_hi[(size_t)B_ * N1_ * C1_], g_f1T_lo[(size_t)B_ * N1_ * C1_];
__device__ __align__(16) __nv_bfloat16 g_f2T_hi[(size_t)B_ * N2_ * C2_], g_f2T_lo[(size_t)B_ * N2_ * C2_];
__device__ __align__(16) float g_PT[(size_t)B_ * N2_ * O1_];      // P^T [b][n2][o1]
__device__ int   g_idx[B_ * N1_ * 3];
__device__ float g_wgt[B_ * N1_ * 3];

// ============================================================
// portable tensor-core primitives
// ============================================================
__device__ __forceinline__ uint32_t smem_u32(const void* p) {
    uint32_t a;
    asm("{ .reg .u64 t; cvta.to.shared.u64 t, %1; cvt.u32.u64 %0, t; }" : "=r"(a) : "l"(p));
    return a;
}
__device__ __forceinline__ void ldsm4(uint32_t* r, uint32_t addr) {
    asm volatile("ldmatrix.sync.aligned.m8n8.x4.shared.b16 {%0,%1,%2,%3}, [%4];"
                 : "=r"(r[0]), "=r"(r[1]), "=r"(r[2]), "=r"(r[3]) : "r"(addr));
}
__device__ __forceinline__ void mma16816(float* c, const uint32_t* a, uint32_t b0, uint32_t b1) {
    asm volatile(
        "mma.sync.aligned.m16n8k16.row.col.f32.bf16.bf16.f32 "
        "{%0,%1,%2,%3}, {%4,%5,%6,%7}, {%8,%9}, {%0,%1,%2,%3};"
        : "+f"(c[0]), "+f"(c[1]), "+f"(c[2]), "+f"(c[3])
        : "r"(a[0]), "r"(a[1]), "r"(a[2]), "r"(a[3]), "r"(b0), "r"(b1));
}
// split-pack two floats -> bf16x2 hi word, bf16x2 lo word
__device__ __forceinline__ uint32_t splitpack(float a, float b, uint32_t& lo) {
    __nv_bfloat16 ha = __float2bfloat16(a), hb = __float2bfloat16(b);
    __nv_bfloat16 la = __float2bfloat16(a - __bfloat162float(ha));
    __nv_bfloat16 lb = __float2bfloat16(b - __bfloat162float(hb));
    __nv_bfloat162 H2; H2.x = ha; H2.y = hb;
    __nv_bfloat162 L2; L2.x = la; L2.y = lb;
    lo = *(uint32_t*)&L2;
    return *(uint32_t*)&H2;
}

// ============================================================
// FUSED gemm1+gemm2 kernel.
// h1 (bf16 split) lives at smem offset 0; staging region at 135168.
// Stage 1: single-buffered (4 chunks). Stage 2: ping-pong B buffers,
// ONE syncthreads per chunk (STS targets buf[i&1]; laggards read buf[(i-1)&1]).
// ============================================================
#define FSLD 40      // staging pitch (bf16 el)
#define H1P  264     // h1 smem pitch (bf16 el)
#define OTP  132     // out-tile pitch (fp32 el)
#define OF_H1HI 0
#define OF_H1LO 67584
#define OF_OUTT 0            // aliases h1 (dead by epilogue 2)
#define OF_ST   135168       // staging region base
#define S2BUF   40960        // one stage-2 buffer (hi 20480 + lo 20480)
#define FSM_BYTES 217088

__global__ void __launch_bounds__(512, 1) fused12_kernel(float* __restrict__ out) {
    extern __shared__ __align__(16) char fsm[];
    __nv_bfloat16* h1hi = (__nv_bfloat16*)(fsm + OF_H1HI);
    __nv_bfloat16* h1lo = (__nv_bfloat16*)(fsm + OF_H1LO);
    float*         outT = (float*)(fsm + OF_OUTT);
    // stage-1 staging
    __nv_bfloat16* sAhi = (__nv_bfloat16*)(fsm + OF_ST);
    __nv_bfloat16* sAlo = (__nv_bfloat16*)(fsm + OF_ST + 10240);
    __nv_bfloat16* sB1hi = (__nv_bfloat16*)(fsm + OF_ST + 20480);
    __nv_bfloat16* sB1lo = (__nv_bfloat16*)(fsm + OF_ST + 40960);

    const int tid = threadIdx.x, lane = tid & 31, wid = tid >> 5;
    const int warpM = wid >> 2, warpN = wid & 3;
    const int b = blockIdx.y;
    const int pt0 = blockIdx.x * 128;

    const uint32_t h1hiB = smem_u32(h1hi), h1loB = smem_u32(h1lo);

    const int lrow = tid >> 2;          // 0..127
    const int lcol = (tid & 3) * 8;     // 0,8,16,24

    const uint32_t aRowSel = lane & 15;
    const uint32_t aColSel = (lane >> 4) << 3;
    const uint32_t bRow = ((lane >> 4) << 3) + (lane & 7);
    const uint32_t bCol = ((lane >> 3) & 1) << 3;

    // ---------------- stage 1 (single-buffered, 4 chunks) ----------------
    const __nv_bfloat16* Ah = g_f1T_hi + ((size_t)b * N1_ + pt0 + lrow) * C1_ + lcol;
    const __nv_bfloat16* Al = g_f1T_lo + ((size_t)b * N1_ + pt0 + lrow) * C1_ + lcol;
    const __nv_bfloat16* B1h0 = g_W1b_hi + (size_t)lrow * C1_ + lcol;
    const __nv_bfloat16* B1h1 = g_W1b_hi + (size_t)(lrow + 128) * C1_ + lcol;
    const __nv_bfloat16* B1l0 = g_W1b_lo + (size_t)lrow * C1_ + lcol;
    const __nv_bfloat16* B1l1 = g_W1b_lo + (size_t)(lrow + 128) * C1_ + lcol;

    float acc[2][8][4];
    #pragma unroll
    for (int i = 0; i < 2; i++)
        #pragma unroll
        for (int j = 0; j < 8; j++)
            #pragma unroll
            for (int k = 0; k < 4; k++) acc[i][j][k] = 0.f;

    uint4 rA0 = *(const uint4*)Ah,   rA1 = *(const uint4*)Al;
    uint4 rB0 = *(const uint4*)B1h0, rB1 = *(const uint4*)B1h1;
    uint4 rB2 = *(const uint4*)B1l0, rB3 = *(const uint4*)B1l1;

    const uint32_t sAhiB = smem_u32(sAhi), sAloB = smem_u32(sAlo);
    const uint32_t sB1hiB = smem_u32(sB1hi), sB1loB = smem_u32(sB1lo);

    for (int kb = 0; kb < C1_; kb += 32) {
        *(uint4*)&sAhi[lrow * FSLD + lcol] = rA0;
        *(uint4*)&sAlo[lrow * FSLD + lcol] = rA1;
        *(uint4*)&sB1hi[lrow * FSLD + lcol] = rB0;
        *(uint4*)&sB1hi[(lrow + 128) * FSLD + lcol] = rB1;
        *(uint4*)&sB1lo[lrow * FSLD + lcol] = rB2;
        *(uint4*)&sB1lo[(lrow + 128) * FSLD + lcol] = rB3;
        __syncthreads();

        int nk = (kb + 32 < C1_) ? kb + 32 : 0;
        rA0 = *(const uint4*)(Ah + nk);   rA1 = *(const uint4*)(Al + nk);
        rB0 = *(const uint4*)(B1h0 + nk); rB1 = *(const uint4*)(B1h1 + nk);
        rB2 = *(const uint4*)(B1l0 + nk); rB3 = *(const uint4*)(B1l1 + nk);

        #pragma unroll
        for (int ks = 0; ks < 2; ks++) {
            uint32_t ah[2][4], al[2][4];
            #pragma unroll
            for (int mi = 0; mi < 2; mi++) {
                uint32_t off = ((warpM * 32 + mi * 16 + aRowSel) * FSLD + ks * 16 + aColSel) * 2;
                ldsm4(ah[mi], sAhiB + off);
                ldsm4(al[mi], sAloB + off);
            }
            #pragma unroll
            for (int nj = 0; nj < 4; nj++) {
                uint32_t bh[4], bl[4];
                uint32_t off = ((warpN * 64 + nj * 16 + bRow) * FSLD + ks * 16 + bCol) * 2;
                ldsm4(bh, sB1hiB + off);
                ldsm4(bl, sB1loB + off);
                #pragma unroll
                for (int mi = 0; mi < 2; mi++)
                    #pragma unroll
                    for (int sub = 0; sub < 2; sub++) {
                        int ni = nj * 2 + sub;
                        uint32_t b0 = bh[sub * 2], b1 = bh[sub * 2 + 1];
                        uint32_t c0_ = bl[sub * 2], c1_ = bl[sub * 2 + 1];
                        mma16816(acc[mi][ni], ah[mi], b0, b1);
                        mma16816(acc[mi][ni], ah[mi], c0_, c1_);
                        mma16816(acc[mi][ni], al[mi], b0, b1);
                    }
            }
        }
        __syncthreads();
    }

    // prefetch stage-2 W2 chunk 0 during gather epilogue
    const __nv_bfloat16* B2h0 = g_W2_hi + (size_t)lrow * O1_ + lcol;
    const __nv_bfloat16* B2h1 = g_W2_hi + (size_t)(lrow + 128) * O1_ + lcol;
    const __nv_bfloat16* B2l0 = g_W2_lo + (size_t)lrow * O1_ + lcol;
    const __nv_bfloat16* B2l1 = g_W2_lo + (size_t)(lrow + 128) * O1_ + lcol;
    rB0 = *(const uint4*)B2h0; rB1 = *(const uint4*)B2h1;
    rB2 = *(const uint4*)B2l0; rB3 = *(const uint4*)B2l1;

    // ---------------- epilogue 1: gather + bias + relu -> h1 smem ----------------
    {
        const int r0 = lane >> 2;
        const int c0 = (lane & 3) * 2;
        const int*   IX = g_idx + (size_t)b * N1_ * 3;
        const float* WG = g_wgt + (size_t)b * N1_ * 3;
        const float* PT = g_PT + (size_t)b * N2_ * O1_;
        #pragma unroll
        for (int mi = 0; mi < 2; mi++)
            #pragma unroll
            for (int h = 0; h < 2; h++) {
                int gmL = warpM * 32 + mi * 16 + r0 + h * 8;
                int n = pt0 + gmL;
                int i0 = IX[n * 3], i1 = IX[n * 3 + 1], i2 = IX[n * 3 + 2];
                float w0 = WG[n * 3], w1 = WG[n * 3 + 1], w2 = WG[n * 3 + 2];
                #pragma unroll
                for (int ni = 0; ni < 8; ni++) {
                    int gn = warpN * 64 + ni * 8 + c0;
                    float2 p0 = *(const float2*)&PT[(size_t)i0 * O1_ + gn];
                    float2 p1 = *(const float2*)&PT[(size_t)i1 * O1_ + gn];
                    float2 p2 = *(const float2*)&PT[(size_t)i2 * O1_ + gn];
                    float2 bs = *(const float2*)&g_b1eff[gn];
                    float v0 = acc[mi][ni][h * 2 + 0] + bs.x + w0 * p0.x + w1 * p1.x + w2 * p2.x;
                    float v1 = acc[mi][ni][h * 2 + 1] + bs.y + w0 * p0.y + w1 * p1.y + w2 * p2.y;
                    v0 = fmaxf(v0, 0.f); v1 = fmaxf(v1, 0.f);
                    uint32_t lo, hi = splitpack(v0, v1, lo);
                    *(uint32_t*)&h1hi[gmL * H1P + gn] = hi;
                    *(uint32_t*)&h1lo[gmL * H1P + gn] = lo;
                }
            }
    }
    __syncthreads();   // h1 visible to all warps

    // ---------------- stage 2: ping-pong B, ONE sync per chunk ----------------
    float acc2[2][8][4];
    #pragma unroll
    for (int i = 0; i < 2; i++)
        #pragma unroll
        for (int j = 0; j < 8; j++)
            #pragma unroll
            for (int k = 0; k < 4; k++) acc2[i][j][k] = 0.f;

    for (int it = 0; it < 8; it++) {
        int kb = it * 32;
        __nv_bfloat16* bh = (__nv_bfloat16*)(fsm + OF_ST + (it & 1) * S2BUF);
        __nv_bfloat16* bl = (__nv_bfloat16*)(fsm + OF_ST + (it & 1) * S2BUF + 20480);
        *(uint4*)&bh[lrow * FSLD + lcol] = rB0;
        *(uint4*)&bh[(lrow + 128) * FSLD + lcol] = rB1;
        *(uint4*)&bl[lrow * FSLD + lcol] = rB2;
        *(uint4*)&bl[(lrow + 128) * FSLD + lcol] = rB3;

        int nk = (it < 7) ? kb + 32 : 0;
        rB0 = *(const uint4*)(B2h0 + nk); rB1 = *(const uint4*)(B2h1 + nk);
        rB2 = *(const uint4*)(B2l0 + nk); rB3 = *(const uint4*)(B2l1 + nk);

        __syncthreads();   // chunk it staged by all

        const uint32_t bhB = smem_u32(bh), blB = smem_u32(bl);
        #pragma unroll
        for (int ks = 0; ks < 2; ks++) {
            uint32_t ah[2][4], al[2][4];
            #pragma unroll
            for (int mi = 0; mi < 2; mi++) {
                uint32_t off = ((warpM * 32 + mi * 16 + aRowSel) * H1P + kb + ks * 16 + aColSel) * 2;
                ldsm4(ah[mi], h1hiB + off);
                ldsm4(al[mi], h1loB + off);
            }
            #pragma unroll
            for (int nj = 0; nj < 4; nj++) {
                uint32_t bhq[4], blq[4];
                uint32_t off = ((warpN * 64 + nj * 16 + bRow) * FSLD + ks * 16 + bCol) * 2;
                ldsm4(bhq, bhB + off);
                ldsm4(blq, blB + off);
                #pragma unroll
                for (int mi = 0; mi < 2; mi++)
                    #pragma unroll
                    for (int sub = 0; sub < 2; sub++) {
                        int ni = nj * 2 + sub;
                        uint32_t b0 = bhq[sub * 2], b1 = bhq[sub * 2 + 1];
                        uint32_t c0_ = blq[sub * 2], c1_ = blq[sub * 2 + 1];
                        mma16816(acc2[mi][ni], ah[mi], b0, b1);
                        mma16816(acc2[mi][ni], ah[mi], c0_, c1_);
                        mma16816(acc2[mi][ni], al[mi], b0, b1);
                    }
            }
        }
    }
    __syncthreads();   // all mma done before outT overwrites h1

    // ---------------- epilogue 2: transpose through smem, coalesced store ----------------
    {
        const int r0 = lane >> 2;
        const int c0 = (lane & 3) * 2;
        #pragma unroll
        for (int mi = 0; mi < 2; mi++)
            #pragma unroll
            for (int h = 0; h < 2; h++) {
                int gmL = warpM * 32 + mi * 16 + r0 + h * 8;
                #pragma unroll
                for (int ni = 0; ni < 8; ni++) {
                    int gn = warpN * 64 + ni * 8 + c0;
                    float2 bs = *(const float2*)&g_b2eff[gn];
                    outT[(size_t)gn * OTP + gmL]       = fmaxf(acc2[mi][ni][h * 2 + 0] + bs.x, 0.f);
                    outT[(size_t)(gn + 1) * OTP + gmL] = fmaxf(acc2[mi][ni][h * 2 + 1] + bs.y, 0.f);
                }
            }
    }
    __syncthreads();

    float* dst = out + (size_t)b * O2_ * N1_ + pt0;
    for (int i = tid; i < 256 * 32; i += 512) {
        int o2 = i >> 5;
        int c = (i & 31) << 2;
        uint4 v = *(uint4*)&outT[o2 * OTP + c];
        *(uint4*)(dst + (size_t)o2 * N1_ + c) = v;
    }
}

// ============================================================
// gemmP: PT[b][n2][o1] = (f2T @ W1a^T)  (verified core, unchanged)
// ============================================================
__global__ void __launch_bounds__(256, 2) gemmP_kernel() {
    __shared__ __align__(16) __nv_bfloat16 sAhi[64][FSLD],  sAlo[64][FSLD];
    __shared__ __align__(16) __nv_bfloat16 sBhi[128][FSLD], sBlo[128][FSLD];

    const int tid = threadIdx.x, lane = tid & 31, wid = tid >> 5;
    const int warpM = wid >> 2, warpN = wid & 3;
    const int b = blockIdx.z;
    const int Mbase = blockIdx.x * 64, Nbase = blockIdx.y * 128;

    float acc[2][4][4];
    #pragma unroll
    for (int i = 0; i < 2; i++)
        #pragma unroll
        for (int j = 0; j < 4; j++)
            #pragma unroll
            for (int k = 0; k < 4; k++) acc[i][j][k] = 0.f;

    const int lrow = tid >> 2;
    const int lcol = (tid & 3) * 8;

    const __nv_bfloat16* pAhi = g_f2T_hi + ((size_t)b * N2_ + Mbase + lrow) * C2_ + lcol;
    const __nv_bfloat16* pAlo = g_f2T_lo + ((size_t)b * N2_ + Mbase + lrow) * C2_ + lcol;
    const __nv_bfloat16* pBhi0 = g_W1a_hi + (size_t)(Nbase + lrow) * C2_ + lcol;
    const __nv_bfloat16* pBlo0 = g_W1a_lo + (size_t)(Nbase + lrow) * C2_ + lcol;
    const __nv_bfloat16* pBhi1 = g_W1a_hi + (size_t)(Nbase + lrow + 64) * C2_ + lcol;
    const __nv_bfloat16* pBlo1 = g_W1a_lo + (size_t)(Nbase + lrow + 64) * C2_ + lcol;

    const uint32_t aRowA = warpM * 32 + (lane & 15);
    const uint32_t aColA = (lane >> 4) << 3;
    const uint32_t bRowB = warpN * 32 + ((lane >> 4) << 3) + (lane & 7);
    const uint32_t bColB = ((lane >> 3) & 1) << 3;
    const uint32_t sAhiB = smem_u32(&sAhi[0][0]), sAloB = smem_u32(&sAlo[0][0]);
    const uint32_t sBhiB = smem_u32(&sBhi[0][0]), sBloB = smem_u32(&sBlo[0][0]);

    uint4 rA0 = *(const uint4*)pAhi,  rA1 = *(const uint4*)pAlo;
    uint4 rBh0 = *(const uint4*)pBhi0, rBh1 = *(const uint4*)pBhi1;
    uint4 rBl0 = *(const uint4*)pBlo0, rBl1 = *(const uint4*)pBlo1;

    for (int kb = 0; kb < C2_; kb += 32) {
        *(uint4*)&sAhi[lrow][lcol] = rA0;
        *(uint4*)&sAlo[lrow][lcol] = rA1;
        *(uint4*)&sBhi[lrow][lcol] = rBh0;
        *(uint4*)&sBhi[lrow + 64][lcol] = rBh1;
        *(uint4*)&sBlo[lrow][lcol] = rBl0;
        *(uint4*)&sBlo[lrow + 64][lcol] = rBl1;
        __syncthreads();

        int nk = (kb + 32 < C2_) ? kb + 32 : 0;
        rA0 = *(const uint4*)(pAhi + nk);  rA1 = *(const uint4*)(pAlo + nk);
        rBh0 = *(const uint4*)(pBhi0 + nk); rBh1 = *(const uint4*)(pBhi1 + nk);
        rBl0 = *(const uint4*)(pBlo0 + nk); rBl1 = *(const uint4*)(pBlo1 + nk);

        #pragma unroll
        for (int ks = 0; ks < 2; ks++) {
            uint32_t ah[2][4], al[2][4], bh[2][4], bl[2][4];
            #pragma unroll
            for (int mi = 0; mi < 2; mi++) {
                uint32_t off = ((aRowA + mi * 16) * FSLD + ks * 16 + aColA) * 2;
                ldsm4(ah[mi], sAhiB + off);
                ldsm4(al[mi], sAloB + off);
            }
            #pragma unroll
            for (int nj = 0; nj < 2; nj++) {
                uint32_t off = ((bRowB + nj * 16) * FSLD + ks * 16 + bColB) * 2;
                ldsm4(bh[nj], sBhiB + off);
                ldsm4(bl[nj], sBloB + off);
            }
            #pragma unroll
            for (int mi = 0; mi < 2; mi++)
                #pragma unroll
                for (int ni = 0; ni < 4; ni++) {
                    const uint32_t* BH = bh[ni >> 1];
                    const uint32_t* BL = bl[ni >> 1];
                    uint32_t b0 = BH[(ni & 1) * 2], b1 = BH[(ni & 1) * 2 + 1];
                    uint32_t c0_ = BL[(ni & 1) * 2], c1_ = BL[(ni & 1) * 2 + 1];
                    mma16816(acc[mi][ni], ah[mi], b0, b1);
                    mma16816(acc[mi][ni], ah[mi], c0_, c1_);
                    mma16816(acc[mi][ni], al[mi], b0, b1);
                }
        }
        __syncthreads();
    }

    const int r0 = lane >> 2;
    const int c0 = (lane & 3) * 2;
    float* outP = g_PT + (size_t)b * N2_ * O1_;
    #pragma unroll
    for (int mi = 0; mi < 2; mi++)
        #pragma unroll
        for (int h = 0; h < 2; h++) {
            int gm = Mbase + warpM * 32 + mi * 16 + r0 + h * 8;
            #pragma unroll
            for (int ni = 0; ni < 4; ni++) {
                int gn = Nbase + warpN * 32 + ni * 8 + c0;
                *(float2*)&outP[(size_t)gm * O1_ + gn] =
                    make_float2(acc[mi][ni][h * 2], acc[mi][ni][h * 2 + 1]);
            }
        }
}

// ============================================================
// prep: fold BN into W/b, split weights into bf16 hi/lo
// ============================================================
__global__ void prep_kernel(const float* __restrict__ W1, const float* __restrict__ b1,
                            const float* __restrict__ g1, const float* __restrict__ be1,
                            const float* __restrict__ W2, const float* __restrict__ b2,
                            const float* __restrict__ g2, const float* __restrict__ be2) {
    const float rs = 0.99999500003749969f;  // 1/sqrt(1+1e-5)
    int t = blockIdx.x * blockDim.x + threadIdx.x;
    int nt = gridDim.x * blockDim.x;
    for (int i = t; i < O1_ * C2_; i += nt) {
        int o = i / C2_;
        float w = W1[o * (C1_ + C2_) + (i % C2_)] * g1[o] * rs;
        __nv_bfloat16 hi = __float2bfloat16(w);
        g_W1a_hi[i] = hi;
        g_W1a_lo[i] = __float2bfloat16(w - __bfloat162float(hi));
    }
    for (int i = t; i < O1_ * C1_; i += nt) {
        int o = i / C1_;
        float w = W1[o * (C1_ + C2_) + C2_ + (i % C1_)] * g1[o] * rs;
        __nv_bfloat16 hi = __float2bfloat16(w);
        g_W1b_hi[i] = hi;
        g_W1b_lo[i] = __float2bfloat16(w - __bfloat162float(hi));
    }
    for (int i = t; i < O2_ * O1_; i += nt) {
        int o = i / O1_;
        float w = W2[i] * g2[o] * rs;
        __nv_bfloat16 hi = __float2bfloat16(w);
        g_W2_hi[i] = hi;
        g_W2_lo[i] = __float2bfloat16(w - __bfloat162float(hi));
    }
    for (int i = t; i < O1_; i += nt) g_b1eff[i] = g1[i] * rs * b1[i] + be1[i];
    for (int i = t; i < O2_; i += nt) g_b2eff[i] = g2[i] * rs * b2[i] + be2[i];
}

// ============================================================
// COMBO kernel: knn (2 points/thread) + tsplit1 + tsplit2, partitioned
// by blockIdx.x. 256 threads, 32KB shared scratch.
// ============================================================
#define KNN_BLKS  (N1_ / 512 * B_)                    // 128
#define TS1_BLKS  ((N1_ / 32) * (C1_ / 32) * B_)      // 8192
#define TS2_BLKS  ((N2_ / 32) * (C2_ / 32) * B_)      // 4096

__device__ __forceinline__ void knn3_insert(float dd, int m,
                                            float& d0, float& d1, float& d2,
                                            int& j0, int& j1, int& j2) {
    if (dd < d2) {
        if (dd < d1) {
            d2 = d1; j2 = j1;
            if (dd < d0) { d1 = d0; j1 = j0; d0 = dd; j0 = m; }
            else         { d1 = dd; j1 = m; }
        } else { d2 = dd; j2 = m; }
    }
}

__device__ void knn_body(int px, int b, const float* __restrict__ xyz1,
                         const float* __restrict__ xyz2, char* cs) {
    float4* s2 = (float4*)cs;
    const float* q = xyz2 + (size_t)b * N2_ * 3;
    for (int i = threadIdx.x; i < N2_; i += 256) {
        float ax = q[i * 3 + 0], ay = q[i * 3 + 1], az = q[i * 3 + 2];
        s2[i] = make_float4(ax, ay, az, ax * ax + ay * ay + az * az);
    }
    __syncthreads();

    int pA = px * 512 + threadIdx.x;
    int pB = pA + 256;
    const float* ppA = xyz1 + ((size_t)b * N1_ + pA) * 3;
    const float* ppB = xyz1 + ((size_t)b * N1_ + pB) * 3;
    float xA = ppA[0], yA = ppA[1], zA = ppA[2];
    float xB = ppB[0], yB = ppB[1], zB = ppB[2];
    float p2A = xA * xA + yA * yA + zA * zA;
    float p2B = xB * xB + yB * yB + zB * zB;

    float dA0 = 3.4e38f, dA1 = 3.4e38f, dA2 = 3.4e38f;
    float dB0 = 3.4e38f, dB1 = 3.4e38f, dB2 = 3.4e38f;
    int jA0 = 0, jA1 = 0, jA2 = 0, jB0 = 0, jB1 = 0, jB2 = 0;
    #pragma unroll 4
    for (int m = 0; m < N2_; m++) {
        float4 v = s2[m];
        float ddA = (p2A + v.w) - 2.0f * (xA * v.x + yA * v.y + zA * v.z);
        float ddB = (p2B + v.w) - 2.0f * (xB * v.x + yB * v.y + zB * v.z);
        knn3_insert(ddA, m, dA0, dA1, dA2, jA0, jA1, jA2);
        knn3_insert(ddB, m, dB0, dB1, dB2, jB0, jB1, jB2);
    }
    #pragma unroll
    for (int s = 0; s < 2; s++) {
        float d0 = s ? dB0 : dA0, d1 = s ? dB1 : dA1, d2 = s ? dB2 : dA2;
        int   j0 = s ? jB0 : jA0, j1 = s ? jB1 : jA1, j2 = s ? jB2 : jA2;
        int   p  = s ? pB : pA;
        float w0 = 1.0f / fmaxf(sqrtf(fmaxf(d0, 0.f)), 1e-8f);
        float w1 = 1.0f / fmaxf(sqrtf(fmaxf(d1, 0.f)), 1e-8f);
        float w2 = 1.0f / fmaxf(sqrtf(fmaxf(d2, 0.f)), 1e-8f);
        float inv = 1.0f / (w0 + w1 + w2);
        size_t base = ((size_t)b * N1_ + p) * 3;
        g_idx[base + 0] = j0; g_idx[base + 1] = j1; g_idx[base + 2] = j2;
        g_wgt[base + 0] = w0 * inv; g_wgt[base + 1] = w1 * inv; g_wgt[base + 2] = w2 * inv;
    }
}

__device__ void tsplit_body(int n_t, int c_t, int b,
                            const float* __restrict__ src,
                            __nv_bfloat16* __restrict__ dhi,
                            __nv_bfloat16* __restrict__ dlo,
                            int C, int Np, char* cs) {
    float (*t)[33] = (float(*)[33])cs;
    int n0 = n_t * 32, c0 = c_t * 32;
    int tx = threadIdx.x & 31, ty = threadIdx.x >> 5;
    #pragma unroll
    for (int r = 0; r < 4; r++) {
        int c = c0 + ty + r * 8;
        t[ty + r * 8][tx] = src[((size_t)b * C + c) * Np + n0 + tx];
    }
    __syncthreads();
    #pragma unroll
    for (int r = 0; r < 4; r++) {
        int n = n0 + ty + r * 8;
        int c = c0 + tx;
        float v = t[tx][ty + r * 8];
        __nv_bfloat16 hi = __float2bfloat16(v);
        size_t o = ((size_t)b * Np + n) * C + c;
        dhi[o] = hi;
        dlo[o] = __float2bfloat16(v - __bfloat162float(hi));
    }
}

__global__ void __launch_bounds__(256) combo_kernel(const float* __restrict__ xyz1,
                                                    const float* __restrict__ xyz2,
                                                    const float* __restrict__ feats1,
                                                    const float* __restrict__ feats2) {
    __shared__ __align__(16) char cs[32768];
    int bid = blockIdx.x;
    if (bid < KNN_BLKS) {
        knn_body(bid & (N1_ / 512 - 1), bid >> 4, xyz1, xyz2, cs);
        return;
    }
    bid -= KNN_BLKS;
    if (bid < TS1_BLKS) {
        int n_t = bid & 255, c_t = (bid >> 8) & 3, b = bid >> 10;
        tsplit_body(n_t, c_t, b, feats1, g_f1T_hi, g_f1T_lo, C1_, N1_, cs);
        return;
    }
    bid -= TS1_BLKS;
    {
        int n_t = bid & 63, c_t = (bid >> 6) & 7, b = bid >> 9;
        tsplit_body(n_t, c_t, b, feats2, g_f2T_hi, g_f2T_lo, C2_, N2_, cs);
    }
}

// ============================================================
extern "C" void kernel_launch(void* const* d_in, const int* in_sizes, int n_in,
                              void* d_out, int out_size) {
    const float* xyz1   = (const float*)d_in[0];
    const float* xyz2   = (const float*)d_in[1];
    const float* feats1 = (const float*)d_in[2];
    const float* feats2 = (const float*)d_in[3];
    const float* W1     = (const float*)d_in[4];
    const float* b1     = (const float*)d_in[5];
    const float* g1     = (const float*)d_in[6];
    const float* be1    = (const float*)d_in[7];
    const float* W2     = (const float*)d_in[8];
    const float* b2     = (const float*)d_in[9];
    const float* g2     = (const float*)d_in[10];
    const float* be2    = (const float*)d_in[11];
    float* out = (float*)d_out;

    cudaFuncSetAttribute(fused12_kernel, cudaFuncAttributeMaxDynamicSharedMemorySize, FSM_BYTES);

    prep_kernel<<<64, 256>>>(W1, b1, g1, be1, W2, b2, g2, be2);              // idx 0
    combo_kernel<<<KNN_BLKS + TS1_BLKS + TS2_BLKS, 256>>>(xyz1, xyz2, feats1, feats2); // idx 1
    gemmP_kernel<<<dim3(N2_ / 64, O1_ / 128, B_), 256>>>();                  // idx 2
    fused12_kernel<<<dim3(N1_ / 128, B_), 512, FSM_BYTES>>>(out);            // idx 3 -> ncu
}